// round 4
// baseline (speedup 1.0000x reference)
#include <cuda_runtime.h>

#define NN   50000
#define FD   96
#define LATD 48
#define EMAX 800000

// ---- device scratch ----
__device__ float sg_msg1[NN * FD];    // x @ w1_l^T
__device__ float sg_hid[NN * FD];     // layer-1 output z
__device__ float sg_msg2[NN * LATD];  // z @ w2_l^T
__device__ float sg_agg[NN * FD];     // gather result (shared by both layers)
__device__ int   sg_deg[NN];
__device__ int   sg_rowptr[NN + 1];
__device__ int   sg_cursor[NN];
__device__ int   sg_adj[EMAX];
__device__ int   sg_src[EMAX];
__device__ int   sg_dst[EMAX];
__device__ int   sg_is64;

// ---- dtype sniff: int64 edge data has zero high-words at odd int32 slots ----
__global__ void sg_detect(const int* __restrict__ ei32, int n32) {
    if (threadIdx.x == 0 && blockIdx.x == 0) {
        int nz = 0;
        int lim = (n32 < 1024) ? n32 : 1024;
        for (int i = 1; i < lim; i += 2) nz |= (ei32[i] != 0);
        sg_is64 = nz ? 0 : 1;   // all odd slots zero -> int64
    }
}

// ---- normalize edges to clamped int32 (also zero deg) ----
__global__ void sg_normalize(const void* __restrict__ ei, int E) {
    int stride = gridDim.x * blockDim.x;
    int is64 = sg_is64;
    for (int e = blockIdx.x * blockDim.x + threadIdx.x; e < E; e += stride) {
        int s, d;
        if (is64) {
            const long long* q = (const long long*)ei;
            s = (int)q[e];
            d = (int)q[e + E];
        } else {
            const int* q = (const int*)ei;
            s = q[e];
            d = q[e + E];
        }
        s = min(max(s, 0), NN - 1);
        d = min(max(d, 0), NN - 1);
        sg_src[e] = s;
        sg_dst[e] = d;
    }
    for (int i = blockIdx.x * blockDim.x + threadIdx.x; i < NN; i += stride)
        sg_deg[i] = 0;
}

__global__ void sg_count(int E) {
    int stride = gridDim.x * blockDim.x;
    for (int e = blockIdx.x * blockDim.x + threadIdx.x; e < E; e += stride)
        atomicAdd(&sg_deg[sg_dst[e]], 1);
}

// One block, 1024 threads: exclusive scan of sg_deg -> rowptr, cursor.
__global__ void __launch_bounds__(1024) sg_scan() {
    __shared__ int part[1024];
    const int CH = (NN + 1023) >> 10;   // 49
    int t = threadIdx.x;
    int base = t * CH;
    int s = 0;
    for (int i = 0; i < CH; i++) {
        int idx = base + i;
        if (idx < NN) s += sg_deg[idx];
    }
    part[t] = s;
    __syncthreads();
    for (int off = 1; off < 1024; off <<= 1) {
        int add = (t >= off) ? part[t - off] : 0;
        __syncthreads();
        part[t] += add;
        __syncthreads();
    }
    int run = part[t] - s;
    for (int i = 0; i < CH; i++) {
        int idx = base + i;
        if (idx < NN) {
            sg_rowptr[idx] = run;
            sg_cursor[idx] = run;
            run += sg_deg[idx];
        }
    }
    if (t == 1023) sg_rowptr[NN] = part[1023];
}

__global__ void sg_bucket(int E) {
    int stride = gridDim.x * blockDim.x;
    for (int e = blockIdx.x * blockDim.x + threadIdx.x; e < E; e += stride) {
        int d = sg_dst[e];
        int p = atomicAdd(&sg_cursor[d], 1);
        sg_adj[p] = sg_src[e];
    }
}

// ---- gather: warp per node, sum rows of V over in-edges ----
template <int OUT, int VSEL>
__global__ void __launch_bounds__(256) sg_gather() {
    int gw = (int)((blockIdx.x * (unsigned)blockDim.x + threadIdx.x) >> 5);
    int lane = threadIdx.x & 31;
    if (gw >= NN) return;
    int beg = sg_rowptr[gw], end = sg_rowptr[gw + 1];
    const float* V = (VSEL == 0) ? sg_msg1 : sg_msg2;

    float a0 = 0.f, a1 = 0.f, a2 = 0.f;
    float b0 = 0.f, b1 = 0.f, b2 = 0.f;
    int j = beg;
    for (; j + 1 < end; j += 2) {
        const float* r0 = V + (size_t)sg_adj[j] * OUT;
        const float* r1 = V + (size_t)sg_adj[j + 1] * OUT;
        a0 += r0[lane];
        b0 += r1[lane];
        if (OUT > 64 || lane < OUT - 32) { a1 += r0[lane + 32]; b1 += r1[lane + 32]; }
        if (OUT > 64)                    { a2 += r0[lane + 64]; b2 += r1[lane + 64]; }
    }
    if (j < end) {
        const float* r0 = V + (size_t)sg_adj[j] * OUT;
        a0 += r0[lane];
        if (OUT > 64 || lane < OUT - 32) a1 += r0[lane + 32];
        if (OUT > 64)                    a2 += r0[lane + 64];
    }
    float* A = sg_agg + (size_t)gw * OUT;
    A[lane] = a0 + b0;
    if (OUT > 64 || lane < OUT - 32) A[lane + 32] = a1 + b1;
    if (OUT > 64)                    A[lane + 64] = a2 + b2;
}

// ---- GEMM: warp per row. out[row,o] = sum_k X[row,k]*W[o,k] (+ epilogue) ----
// EPI: 0 plain; 1 +bias +agg/deg, relu; 2 +bias +agg/deg.
// XSEL: -1 external, 0 sg_hid.  OSEL: -1 external, 0 sg_msg1, 1 sg_hid, 2 sg_msg2.
template <int OUT, int EPI, int XSEL, int OSEL>
__global__ void __launch_bounds__(256) sg_gemm(const float* __restrict__ Xin,
                                               const float* __restrict__ W,
                                               const float* __restrict__ bias,
                                               float* __restrict__ Oin) {
    __shared__ float ws[FD * 97];
    __shared__ float xs[8][FD];
    const float* X = (XSEL < 0) ? Xin : sg_hid;
    float* O;
    if (OSEL < 0) O = Oin;
    else if (OSEL == 0) O = sg_msg1;
    else if (OSEL == 1) O = sg_hid;
    else O = sg_msg2;

    int tid = threadIdx.x;
    for (int i = tid; i < OUT * FD; i += 256)
        ws[(i / FD) * 97 + (i % FD)] = W[i];
    __syncthreads();

    int warp = tid >> 5, lane = tid & 31;
    int row = blockIdx.x * 8 + warp;
    if (row >= NN) return;

    xs[warp][lane]      = X[(size_t)row * FD + lane];
    xs[warp][lane + 32] = X[(size_t)row * FD + lane + 32];
    xs[warp][lane + 64] = X[(size_t)row * FD + lane + 64];
    __syncwarp();

    float a0 = 0.f, a1 = 0.f, a2 = 0.f;
#pragma unroll
    for (int k = 0; k < FD; k++) {
        float xk = xs[warp][k];
        a0 = fmaf(ws[lane * 97 + k], xk, a0);
        a1 = fmaf(ws[(lane + 32) * 97 + k], xk, a1);
        if (OUT > 64) a2 = fmaf(ws[(lane + 64) * 97 + k], xk, a2);
    }

    if (EPI == 0) {
        O[(size_t)row * OUT + lane] = a0;
        if (OUT > 64) {
            O[(size_t)row * OUT + lane + 32] = a1;
            O[(size_t)row * OUT + lane + 64] = a2;
        } else if (lane < OUT - 32) {
            O[(size_t)row * OUT + lane + 32] = a1;
        }
    } else {
        float inv = 1.f / fmaxf((float)sg_deg[row], 1.f);
        float v0 = a0 + bias[lane] + sg_agg[(size_t)row * OUT + lane] * inv;
        if (EPI == 1) v0 = fmaxf(v0, 0.f);
        O[(size_t)row * OUT + lane] = v0;

        if (OUT > 64) {
            float v1 = a1 + bias[lane + 32] + sg_agg[(size_t)row * OUT + lane + 32] * inv;
            float v2 = a2 + bias[lane + 64] + sg_agg[(size_t)row * OUT + lane + 64] * inv;
            if (EPI == 1) { v1 = fmaxf(v1, 0.f); v2 = fmaxf(v2, 0.f); }
            O[(size_t)row * OUT + lane + 32] = v1;
            O[(size_t)row * OUT + lane + 64] = v2;
        } else if (lane < OUT - 32) {
            float v1 = a1 + bias[lane + 32] + sg_agg[(size_t)row * OUT + lane + 32] * inv;
            if (EPI == 1) v1 = fmaxf(v1, 0.f);
            O[(size_t)row * OUT + lane + 32] = v1;
        }
    }
}

extern "C" void kernel_launch(void* const* d_in, const int* in_sizes, int n_in,
                              void* d_out, int out_size) {
    const float* x    = (const float*)d_in[0];
    const void*  ei   = d_in[1];
    const float* w1_l = (const float*)d_in[2];
    const float* b1   = (const float*)d_in[3];
    const float* w1_r = (const float*)d_in[4];
    const float* w2_l = (const float*)d_in[5];
    const float* b2   = (const float*)d_in[6];
    const float* w2_r = (const float*)d_in[7];
    float*       out  = (float*)d_out;

    int E = in_sizes[1] / 2;
    if (E > EMAX) E = EMAX;

    const int gemm_blocks = (NN + 7) / 8;            // warp per row
    const int gath_blocks = (NN * 32 + 255) / 256;   // warp per node

    // dtype sniff + edge normalization (clamped int32), then CSR build
    sg_detect<<<1, 32>>>((const int*)ei, in_sizes[1]);
    sg_normalize<<<1024, 256>>>(ei, E);
    sg_count<<<1024, 256>>>(E);
    sg_scan<<<1, 1024>>>();
    sg_bucket<<<1024, 256>>>(E);

    // Layer 1: msg1 = x@w1_l^T ; agg = gather(msg1) ; hid = relu(agg/deg + b1 + x@w1_r^T)
    sg_gemm<96, 0, -1, 0><<<gemm_blocks, 256>>>(x, w1_l, nullptr, nullptr);
    sg_gather<96, 0><<<gath_blocks, 256>>>();
    sg_gemm<96, 1, -1, 1><<<gemm_blocks, 256>>>(x, w1_r, b1, nullptr);

    // Layer 2 (aggregate in 48-wide latent space):
    sg_gemm<48, 0, 0, 2><<<gemm_blocks, 256>>>(nullptr, w2_l, nullptr, nullptr);
    sg_gather<48, 1><<<gath_blocks, 256>>>();
    sg_gemm<48, 2, 0, -1><<<gemm_blocks, 256>>>(nullptr, w2_r, b2, out);
}

// round 5
// speedup vs baseline: 1.7783x; 1.7783x over previous
#include <cuda_runtime.h>

#define NN   50000
#define FD   96
#define LATD 48
#define EMAX 800000
#define SCAN_BLK 512
#define SCAN_NB  ((NN + SCAN_BLK - 1) / SCAN_BLK)   // 98

// ---- device scratch ----
__device__ __align__(16) float sg_msg1[NN * FD];    // x @ w1_l^T
__device__ __align__(16) float sg_hid[NN * FD];     // layer-1 output z
__device__ __align__(16) float sg_msg2[NN * LATD];  // z @ w2_l^T
__device__ __align__(16) float sg_agg[NN * FD];     // gather result
__device__ int sg_deg[NN];
__device__ int sg_rowptr[NN + 1];
__device__ int sg_cursor[NN];
__device__ int sg_adj[EMAX];
__device__ int sg_src[EMAX];
__device__ int sg_dst[EMAX];
__device__ int sg_part[SCAN_NB];
__device__ int sg_off[SCAN_NB];
__device__ int sg_is64;

// ---- dtype sniff: int64 edges have all-zero high words ----
__global__ void sg_detect(const int* __restrict__ ei32, int n32) {
    if (threadIdx.x == 0) {
        int nz = 0;
        int lim = (n32 < 1024) ? n32 : 1024;
        for (int i = 1; i < lim; i += 2) nz |= (ei32[i] != 0);
        sg_is64 = nz ? 0 : 1;
    }
}

__global__ void sg_zero_deg() {
    int i = blockIdx.x * blockDim.x + threadIdx.x;
    if (i < NN) sg_deg[i] = 0;
}

// ---- normalize edges to clamped int32 AND count degrees (fused) ----
__global__ void sg_norm_count(const void* __restrict__ ei, int E) {
    int stride = gridDim.x * blockDim.x;
    int is64 = sg_is64;
    for (int e = blockIdx.x * blockDim.x + threadIdx.x; e < E; e += stride) {
        int s, d;
        if (is64) {
            const long long* q = (const long long*)ei;
            s = (int)q[e];
            d = (int)q[e + E];
        } else {
            const int* q = (const int*)ei;
            s = q[e];
            d = q[e + E];
        }
        s = min(max(s, 0), NN - 1);
        d = min(max(d, 0), NN - 1);
        sg_src[e] = s;
        sg_dst[e] = d;
        atomicAdd(&sg_deg[d], 1);
    }
}

// ---- 3-phase scan ----
__global__ void __launch_bounds__(SCAN_BLK) sg_scan_a() {
    __shared__ int sm[SCAN_BLK];
    int t = threadIdx.x;
    int i = blockIdx.x * SCAN_BLK + t;
    sm[t] = (i < NN) ? sg_deg[i] : 0;
    __syncthreads();
    for (int off = SCAN_BLK / 2; off > 0; off >>= 1) {
        if (t < off) sm[t] += sm[t + off];
        __syncthreads();
    }
    if (t == 0) sg_part[blockIdx.x] = sm[0];
}

__global__ void __launch_bounds__(128) sg_scan_b() {
    __shared__ int sm[128];
    int t = threadIdx.x;
    int v = (t < SCAN_NB) ? sg_part[t] : 0;
    sm[t] = v;
    __syncthreads();
    for (int off = 1; off < 128; off <<= 1) {
        int add = (t >= off) ? sm[t - off] : 0;
        __syncthreads();
        sm[t] += add;
        __syncthreads();
    }
    if (t < SCAN_NB) sg_off[t] = sm[t] - v;
    if (t == 127) sg_rowptr[NN] = sm[127];
}

__global__ void __launch_bounds__(SCAN_BLK) sg_scan_c() {
    __shared__ int sm[SCAN_BLK];
    int t = threadIdx.x;
    int i = blockIdx.x * SCAN_BLK + t;
    int v = (i < NN) ? sg_deg[i] : 0;
    sm[t] = v;
    __syncthreads();
    for (int off = 1; off < SCAN_BLK; off <<= 1) {
        int add = (t >= off) ? sm[t - off] : 0;
        __syncthreads();
        sm[t] += add;
        __syncthreads();
    }
    if (i < NN) {
        int excl = sg_off[blockIdx.x] + sm[t] - v;
        sg_rowptr[i] = excl;
        sg_cursor[i] = excl;
    }
}

__global__ void sg_bucket(int E) {
    int stride = gridDim.x * blockDim.x;
    for (int e = blockIdx.x * blockDim.x + threadIdx.x; e < E; e += stride) {
        int p = atomicAdd(&sg_cursor[sg_dst[e]], 1);
        sg_adj[p] = sg_src[e];
    }
}

// ---- gather: sub-warp per node, float4 rows ----
// OUT=96: 32 lanes/node (24 active). OUT=48: 16 lanes/node (12 active).
template <int OUT, int VSEL>
__global__ void __launch_bounds__(256) sg_gather() {
    const int SUBW = (OUT == 96) ? 32 : 16;
    const int VQ = OUT / 4;
    int t = blockIdx.x * 256 + threadIdx.x;
    int node = t / SUBW;
    int sl = t % SUBW;
    if (node >= NN || sl >= VQ) return;
    const float4* V = (const float4*)((VSEL == 0) ? sg_msg1 : sg_msg2);
    int beg = sg_rowptr[node], end = sg_rowptr[node + 1];

    float4 a = make_float4(0.f, 0.f, 0.f, 0.f);
    float4 b = make_float4(0.f, 0.f, 0.f, 0.f);
    int j = beg;
    for (; j + 1 < end; j += 2) {
        float4 r0 = V[(size_t)sg_adj[j] * VQ + sl];
        float4 r1 = V[(size_t)sg_adj[j + 1] * VQ + sl];
        a.x += r0.x; a.y += r0.y; a.z += r0.z; a.w += r0.w;
        b.x += r1.x; b.y += r1.y; b.z += r1.z; b.w += r1.w;
    }
    if (j < end) {
        float4 r0 = V[(size_t)sg_adj[j] * VQ + sl];
        a.x += r0.x; a.y += r0.y; a.z += r0.z; a.w += r0.w;
    }
    float4 s = make_float4(a.x + b.x, a.y + b.y, a.z + b.z, a.w + b.w);
    ((float4*)sg_agg)[(size_t)node * VQ + sl] = s;
}

// ---- register-tiled GEMM: thread = 4 rows x 4 outputs ----
// EPI: 0 plain; 1 +bias +agg/deg, relu; 2 +bias +agg/deg.
// XSEL: -1 external, 0 sg_hid.  OSEL: -1 external, 0 sg_msg1, 1 sg_hid, 2 sg_msg2.
template <int OUT, int EPI, int XSEL, int OSEL>
__global__ void sg_gemm_rt(const float* __restrict__ Xin,
                           const float* __restrict__ W,
                           const float* __restrict__ bias,
                           float* __restrict__ Oin) {
    const int TQ = OUT / 4;                    // 24 or 12
    const int TY = (OUT == 96) ? 4 : 16;
    const int THREADS = TQ * TY;               // 96 or 192
    const int ROWS = TY * 4;                   // 16 or 64
    const int WP = OUT + 4;                    // padded k-row stride (floats)

    __shared__ __align__(16) float ws[FD * WP];
    __shared__ __align__(16) float xs[ROWS * FD];

    const float* X = (XSEL < 0) ? Xin : sg_hid;
    float* O;
    if (OSEL < 0) O = Oin;
    else if (OSEL == 0) O = sg_msg1;
    else if (OSEL == 1) O = sg_hid;
    else O = sg_msg2;

    int tid = threadIdx.x;
    int R0 = blockIdx.x * ROWS;

    // W[o][k] -> ws[k][o] (coalesced global read; 4-way smem write conflict OK)
    for (int i = tid; i < OUT * FD; i += THREADS) {
        int o = i / FD, k = i % FD;
        ws[k * WP + o] = W[i];
    }
    // X tile (float4 copy)
    {
        float4* xs4 = (float4*)xs;
        const int CNT = ROWS * FD / 4;
        for (int i = tid; i < CNT; i += THREADS) {
            int row = R0 + (i * 4) / FD;
            xs4[i] = (row < NN) ? ((const float4*)(X + (size_t)R0 * FD))[i]
                                : make_float4(0.f, 0.f, 0.f, 0.f);
        }
    }
    __syncthreads();

    int tx = tid % TQ, ty = tid / TQ;
    int r0 = ty * 4;

    float4 acc0 = make_float4(0.f, 0.f, 0.f, 0.f);
    float4 acc1 = acc0, acc2 = acc0, acc3 = acc0;

#pragma unroll 4
    for (int k = 0; k < FD; k++) {
        float4 w = *(const float4*)&ws[k * WP + tx * 4];
        float x0 = xs[(r0 + 0) * FD + k];
        float x1 = xs[(r0 + 1) * FD + k];
        float x2 = xs[(r0 + 2) * FD + k];
        float x3 = xs[(r0 + 3) * FD + k];
        acc0.x = fmaf(w.x, x0, acc0.x); acc0.y = fmaf(w.y, x0, acc0.y);
        acc0.z = fmaf(w.z, x0, acc0.z); acc0.w = fmaf(w.w, x0, acc0.w);
        acc1.x = fmaf(w.x, x1, acc1.x); acc1.y = fmaf(w.y, x1, acc1.y);
        acc1.z = fmaf(w.z, x1, acc1.z); acc1.w = fmaf(w.w, x1, acc1.w);
        acc2.x = fmaf(w.x, x2, acc2.x); acc2.y = fmaf(w.y, x2, acc2.y);
        acc2.z = fmaf(w.z, x2, acc2.z); acc2.w = fmaf(w.w, x2, acc2.w);
        acc3.x = fmaf(w.x, x3, acc3.x); acc3.y = fmaf(w.y, x3, acc3.y);
        acc3.z = fmaf(w.z, x3, acc3.z); acc3.w = fmaf(w.w, x3, acc3.w);
    }

    float4 accs[4] = {acc0, acc1, acc2, acc3};
#pragma unroll
    for (int i = 0; i < 4; i++) {
        int row = R0 + r0 + i;
        if (row >= NN) break;
        float4 v = accs[i];
        if (EPI != 0) {
            float inv = 1.f / fmaxf((float)sg_deg[row], 1.f);
            float4 ag = *(const float4*)&sg_agg[(size_t)row * OUT + tx * 4];
            float4 bb = *(const float4*)&bias[tx * 4];
            v.x += bb.x + ag.x * inv;
            v.y += bb.y + ag.y * inv;
            v.z += bb.z + ag.z * inv;
            v.w += bb.w + ag.w * inv;
            if (EPI == 1) {
                v.x = fmaxf(v.x, 0.f); v.y = fmaxf(v.y, 0.f);
                v.z = fmaxf(v.z, 0.f); v.w = fmaxf(v.w, 0.f);
            }
        }
        *(float4*)&O[(size_t)row * OUT + tx * 4] = v;
    }
}

extern "C" void kernel_launch(void* const* d_in, const int* in_sizes, int n_in,
                              void* d_out, int out_size) {
    const float* x    = (const float*)d_in[0];
    const void*  ei   = d_in[1];
    const float* w1_l = (const float*)d_in[2];
    const float* b1   = (const float*)d_in[3];
    const float* w1_r = (const float*)d_in[4];
    const float* w2_l = (const float*)d_in[5];
    const float* b2   = (const float*)d_in[6];
    const float* w2_r = (const float*)d_in[7];
    float*       out  = (float*)d_out;

    int E = in_sizes[1] / 2;
    if (E > EMAX) E = EMAX;

    const int g96_blocks = (NN + 15) / 16;            // ROWS=16
    const int g48_blocks = (NN + 63) / 64;            // ROWS=64
    const int ga96_blocks = (NN * 32 + 255) / 256;
    const int ga48_blocks = (NN * 16 + 255) / 256;

    // CSR build
    sg_detect<<<1, 32>>>((const int*)ei, in_sizes[1]);
    sg_zero_deg<<<SCAN_NB, SCAN_BLK>>>();
    sg_norm_count<<<1024, 256>>>(ei, E);
    sg_scan_a<<<SCAN_NB, SCAN_BLK>>>();
    sg_scan_b<<<1, 128>>>();
    sg_scan_c<<<SCAN_NB, SCAN_BLK>>>();
    sg_bucket<<<1024, 256>>>(E);

    // Layer 1: msg1 = x@w1_l^T ; agg = gather(msg1) ; hid = relu(agg/deg + b1 + x@w1_r^T)
    sg_gemm_rt<96, 0, -1, 0><<<g96_blocks, 96>>>(x, w1_l, nullptr, nullptr);
    sg_gather<96, 0><<<ga96_blocks, 256>>>();
    sg_gemm_rt<96, 1, -1, 1><<<g96_blocks, 96>>>(x, w1_r, b1, nullptr);

    // Layer 2 (48-wide latent aggregation)
    sg_gemm_rt<48, 0, 0, 2><<<g48_blocks, 192>>>(nullptr, w2_l, nullptr, nullptr);
    sg_gather<48, 1><<<ga48_blocks, 256>>>();
    sg_gemm_rt<48, 2, 0, -1><<<g48_blocks, 192>>>(nullptr, w2_r, b2, out);
}